// round 1
// baseline (speedup 1.0000x reference)
#include <cuda_runtime.h>

// EpochedFutureFill == causal FIR conv, B=256, T=L=65536.
// y = first T samples of linear conv(x, filt) via FFT of size N=131072 = 4 * 8^5.
// Real-pair packing: z_p = x[p] + i*x[p+128]; FFT(z)*F = FFT(y_p + i*y_{p+128}).
// Stockham autosort mixed-radix FFT, 6 passes fwd (129 rows), 6 passes inv (128 rows),
// with pack / spectrum-multiply / unpack fused into the boundary stages.

namespace {
constexpr int N_FFT = 131072;
constexpr int T_LEN = 65536;
constexpr int PAIRS = 128;   // packed complex rows
constexpr int ROWS_F = 129;  // pairs + filter row
constexpr int NQ = N_FFT / 4;  // 32768
constexpr int NE = N_FFT / 8;  // 16384
constexpr float INV_N = 1.0f / (float)N_FFT;
constexpr float TWO_PI = 6.28318530717958647692f;
}

// Scratch ping-pong buffers (135 MB each). __device__ globals are the allowed
// scratch mechanism (no cudaMalloc permitted anywhere).
__device__ float2 g_bufA[(size_t)ROWS_F * N_FFT];
__device__ float2 g_bufB[(size_t)ROWS_F * N_FFT];

__device__ __forceinline__ float2 cadd(float2 a, float2 b) { return make_float2(a.x + b.x, a.y + b.y); }
__device__ __forceinline__ float2 csub(float2 a, float2 b) { return make_float2(a.x - b.x, a.y - b.y); }
__device__ __forceinline__ float2 cmul(float2 a, float2 b) {
    return make_float2(fmaf(a.x, b.x, -a.y * b.y), fmaf(a.x, b.y, a.y * b.x));
}

// multiply by (i * DIR): DIR=-1 (fwd) -> -i ; DIR=+1 (inv) -> +i
template <int DIR>
__device__ __forceinline__ float2 cmuli(float2 a) {
    return (DIR < 0) ? make_float2(a.y, -a.x) : make_float2(-a.y, a.x);
}

template <int DIR>
__device__ __forceinline__ void dft4(float2 v[4]) {
    float2 t0 = cadd(v[0], v[2]);
    float2 t1 = cadd(v[1], v[3]);
    float2 t2 = csub(v[0], v[2]);
    float2 t3 = cmuli<DIR>(csub(v[1], v[3]));
    v[0] = cadd(t0, t1);
    v[2] = csub(t0, t1);
    v[1] = cadd(t2, t3);
    v[3] = csub(t2, t3);
}

template <int DIR>
__device__ __forceinline__ void dft8(float2 v[8]) {
    const float C = 0.70710678118654752440f;
    float2 b[4], d[4];
#pragma unroll
    for (int i = 0; i < 4; i++) {
        b[i] = cadd(v[i], v[i + 4]);
        d[i] = csub(v[i], v[i + 4]);
    }
    d[1] = cmul(d[1], make_float2(C, (float)DIR * C));
    d[2] = cmuli<DIR>(d[2]);
    d[3] = cmul(d[3], make_float2(-C, (float)DIR * C));
    dft4<DIR>(b);
    dft4<DIR>(d);
    v[0] = b[0]; v[2] = b[1]; v[4] = b[2]; v[6] = b[3];
    v[1] = d[0]; v[3] = d[1]; v[5] = d[2]; v[7] = d[3];
}

// ---------------- Stage 1 (forward): fused zero-pad + pack + radix-4 (Ns=1) ----------------
// Rows 0..127: z[n] = x[row][n] + i*x[row+128][n] (n < T, else 0).
// Row 128:     z[n] = filt[n] (n < T, else 0).
// n = j + r*NQ; r=0,1 are real data, r=2,3 zero (T == 2*NQ).
__global__ void k_pack_r4(const float* __restrict__ x, const float* __restrict__ filt,
                          float2* __restrict__ out) {
    int j = blockIdx.x * blockDim.x + threadIdx.x;  // [0, NQ)
    int row = blockIdx.y;
    float2 v[4];
    if (row < PAIRS) {
        const float* xa = x + (size_t)row * T_LEN;
        const float* xb = x + (size_t)(row + PAIRS) * T_LEN;
        v[0] = make_float2(xa[j], xb[j]);
        v[1] = make_float2(xa[j + NQ], xb[j + NQ]);
    } else {
        v[0] = make_float2(filt[j], 0.0f);
        v[1] = make_float2(filt[j + NQ], 0.0f);
    }
    v[2] = make_float2(0.0f, 0.0f);
    v[3] = make_float2(0.0f, 0.0f);
    dft4<-1>(v);  // Ns=1: no twiddle
    float2* o = out + (size_t)row * N_FFT + (size_t)j * 4;
#pragma unroll
    for (int r = 0; r < 4; r++) o[r] = v[r];
}

// ---------------- Generic Stockham radix-8 stage ----------------
template <int DIR, int NS>
__global__ void k_r8(const float2* __restrict__ in, float2* __restrict__ out) {
    int j = blockIdx.x * blockDim.x + threadIdx.x;  // [0, NE)
    int row = blockIdx.y;
    const float2* inr = in + (size_t)row * N_FFT;
    float2 v[8];
#pragma unroll
    for (int r = 0; r < 8; r++) v[r] = inr[j + r * NE];

    int jm = j & (NS - 1);
    // base angle in [0, 2pi/8) -> high __sincosf accuracy; powers by chained cmul
    float ang = (float)DIR * TWO_PI * (float)jm / (float)(NS * 8);
    float s, c;
    __sincosf(ang, &s, &c);
    float2 w = make_float2(c, s);
    float2 wr = w;
#pragma unroll
    for (int r = 1; r < 8; r++) {
        v[r] = cmul(v[r], wr);
        wr = cmul(wr, w);
    }
    dft8<DIR>(v);
    size_t idxD = (size_t)(j / NS) * (size_t)(NS * 8) + (size_t)jm;
    float2* o = out + (size_t)row * N_FFT;
#pragma unroll
    for (int r = 0; r < 8; r++) o[idxD + (size_t)r * NS] = v[r];
}

// ---------------- Stage 1 (inverse): fused spectrum multiply + 1/N + radix-4 (Ns=1) ---------
__global__ void k_mult_r4(const float2* __restrict__ in, float2* __restrict__ out) {
    int j = blockIdx.x * blockDim.x + threadIdx.x;  // [0, NQ)
    int row = blockIdx.y;                           // [0, PAIRS)
    const float2* Z = in + (size_t)row * N_FFT;
    const float2* F = in + (size_t)PAIRS * N_FFT;  // filter spectrum (row 128), L2-resident
    float2 v[4];
#pragma unroll
    for (int r = 0; r < 4; r++) {
        int n = j + r * NQ;
        float2 p = cmul(Z[n], F[n]);
        v[r] = make_float2(p.x * INV_N, p.y * INV_N);
    }
    dft4<1>(v);  // Ns=1: no twiddle
    float2* o = out + (size_t)row * N_FFT + (size_t)j * 4;
#pragma unroll
    for (int r = 0; r < 4; r++) o[r] = v[r];
}

// ---------------- Last inverse stage (radix-8, Ns=NE) fused with causal unpack -------------
// Output natural index = j + r*NE; keep indices < T (r < 4). Re -> y[row], Im -> y[row+128].
__global__ void k_r8_last(const float2* __restrict__ in, float* __restrict__ y) {
    int j = blockIdx.x * blockDim.x + threadIdx.x;  // [0, NE)
    int row = blockIdx.y;                           // [0, PAIRS)
    const float2* inr = in + (size_t)row * N_FFT;
    float2 v[8];
#pragma unroll
    for (int r = 0; r < 8; r++) v[r] = inr[j + r * NE];

    float ang = TWO_PI * (float)j / (float)N_FFT;  // DIR=+1, jm=j, NS*8 = N
    float s, c;
    __sincosf(ang, &s, &c);
    float2 w = make_float2(c, s);
    float2 wr = w;
#pragma unroll
    for (int r = 1; r < 8; r++) {
        v[r] = cmul(v[r], wr);
        wr = cmul(wr, w);
    }
    dft8<1>(v);
    float* ya = y + (size_t)row * T_LEN;
    float* yb = y + (size_t)(row + PAIRS) * T_LEN;
#pragma unroll
    for (int r = 0; r < 4; r++) {
        int t = j + r * NE;
        ya[t] = v[r].x;
        yb[t] = v[r].y;
    }
}

extern "C" void kernel_launch(void* const* d_in, const int* in_sizes, int n_in,
                              void* d_out, int out_size) {
    const float* x = (const float*)d_in[0];
    const float* filt = (const float*)d_in[1];
    float* y = (float*)d_out;

    float2 *A = nullptr, *B = nullptr;
    cudaGetSymbolAddress((void**)&A, g_bufA);
    cudaGetSymbolAddress((void**)&B, g_bufB);

    dim3 blk(256);
    dim3 gq(NQ / 256, ROWS_F);   // radix-4 fwd grid
    dim3 ge(NE / 256, ROWS_F);   // radix-8 fwd grid
    dim3 gqi(NQ / 256, PAIRS);   // radix-4 inv grid
    dim3 gei(NE / 256, PAIRS);   // radix-8 inv grid

    // Forward: 129 rows, 4 * 8^5 plan. pack->A, then ping-pong; spectrum lands in B.
    k_pack_r4<<<gq, blk>>>(x, filt, A);
    k_r8<-1, 4><<<ge, blk>>>(A, B);
    k_r8<-1, 32><<<ge, blk>>>(B, A);
    k_r8<-1, 256><<<ge, blk>>>(A, B);
    k_r8<-1, 2048><<<ge, blk>>>(B, A);
    k_r8<-1, 16384><<<ge, blk>>>(A, B);

    // Inverse: 128 rows. Multiply by filter spectrum (row 128 of B) + scale, then IFFT.
    k_mult_r4<<<gqi, blk>>>(B, A);
    k_r8<1, 4><<<gei, blk>>>(A, B);
    k_r8<1, 32><<<gei, blk>>>(B, A);
    k_r8<1, 256><<<gei, blk>>>(A, B);
    k_r8<1, 2048><<<gei, blk>>>(B, A);
    k_r8_last<<<gei, blk>>>(A, y);
}

// round 2
// speedup vs baseline: 2.1562x; 2.1562x over previous
#include <cuda_runtime.h>

// EpochedFutureFill == causal FIR conv, B=256, T=L=65536, via FFT of N=131072.
// Four-step decomposition: N = 256 (n1, stride 512) x 512 (n2, contiguous).
//   n = 512*n1 + n2,  k = k1 + 256*k2
//   K1 : pack + FFT256 over n1 (strided) + w_N^{-n2 k1}  -> U[k1][n2]
//   K2f: filter row: FFT512 over n2 -> F[k1][k2] (scaled by 1/N)
//   K23: FFT512 fwd over n2, multiply by F, IFFT512, w_N^{+n2 k1}  (in place)
//   K4 : IFFT256 over k1 (strided) + causal unpack to y
// Real-pair packing: rows (b, b+128) as one complex row; filter real => no unpack.

namespace {
constexpr int N_FFT = 131072;
constexpr int T_LEN = 65536;
constexpr int PAIRS = 128;
constexpr int ROWS_F = 129;
constexpr float TWO_PI = 6.28318530717958647692f;
constexpr float INV_N = 1.0f / (float)N_FFT;
}

// Scratch (no cudaMalloc allowed): 135 MB intermediate + 1 MB filter spectrum.
__device__ float2 g_buf[(size_t)ROWS_F * N_FFT];
__device__ float2 g_fspec[N_FFT];

__device__ __forceinline__ float2 cadd(float2 a, float2 b) { return make_float2(a.x + b.x, a.y + b.y); }
__device__ __forceinline__ float2 csub(float2 a, float2 b) { return make_float2(a.x - b.x, a.y - b.y); }
__device__ __forceinline__ float2 cmul(float2 a, float2 b) {
    return make_float2(fmaf(a.x, b.x, -a.y * b.y), fmaf(a.x, b.y, a.y * b.x));
}
template <int DIR>
__device__ __forceinline__ float2 cmuli(float2 a) {  // * (i*DIR)
    return (DIR < 0) ? make_float2(a.y, -a.x) : make_float2(-a.y, a.x);
}

template <int DIR>
__device__ __forceinline__ void dft4(float2 v[4]) {
    float2 t0 = cadd(v[0], v[2]);
    float2 t1 = cadd(v[1], v[3]);
    float2 t2 = csub(v[0], v[2]);
    float2 t3 = cmuli<DIR>(csub(v[1], v[3]));
    v[0] = cadd(t0, t1);
    v[2] = csub(t0, t1);
    v[1] = cadd(t2, t3);
    v[3] = csub(t2, t3);
}

template <int DIR>
__device__ __forceinline__ void dft8(float2 v[8]) {
    const float C = 0.70710678118654752440f;
    float2 b[4], d[4];
#pragma unroll
    for (int i = 0; i < 4; i++) {
        b[i] = cadd(v[i], v[i + 4]);
        d[i] = csub(v[i], v[i + 4]);
    }
    d[1] = cmul(d[1], make_float2(C, (float)DIR * C));
    d[2] = cmuli<DIR>(d[2]);
    d[3] = cmul(d[3], make_float2(-C, (float)DIR * C));
    dft4<DIR>(b);
    dft4<DIR>(d);
    v[0] = b[0]; v[2] = b[1]; v[4] = b[2]; v[6] = b[3];
    v[1] = d[0]; v[3] = d[1]; v[5] = d[2]; v[7] = d[3];
}

// v[r] *= w^r, w = exp(i * DIR * 2pi * frac)
template <int DIR, int CNT>
__device__ __forceinline__ void twid(float2* v, float frac) {
    float s, c;
    __sincosf((float)DIR * TWO_PI * frac, &s, &c);
    float2 w = make_float2(c, s), wr = w;
#pragma unroll
    for (int r = 1; r < CNT; r++) { v[r] = cmul(v[r], wr); wr = cmul(wr, w); }
}

// smem swizzle for the contiguous-dim 512 FFT (conflict-free scatters)
__device__ __forceinline__ int ph(int n) { return n + (n >> 3); }

// Full 512-pt FFT for one row held by 64 threads (t in [0,64)), 8 values each.
// Entry: v[r] = data[t + 64*r]. Exit: v[r] = DFT[t + 64*r]. s = per-FFT smem (576 float2).
// Caller must ensure smem is free before calling (barrier).
template <int DIR>
__device__ __forceinline__ void fft512(float2* v, float2* s, int t) {
    dft8<DIR>(v);  // stage 1, Ns=1
#pragma unroll
    for (int r = 0; r < 8; r++) s[ph(8 * t + r)] = v[r];
    __syncthreads();
#pragma unroll
    for (int r = 0; r < 8; r++) v[r] = s[ph(t + 64 * r)];
    twid<DIR, 8>(v, (float)(t & 7) * (1.0f / 64.0f));
    dft8<DIR>(v);  // stage 2, Ns=8
    __syncthreads();
    {
        int base = ((t >> 3) << 6) + (t & 7);
#pragma unroll
        for (int r = 0; r < 8; r++) s[ph(base + 8 * r)] = v[r];
    }
    __syncthreads();
#pragma unroll
    for (int r = 0; r < 8; r++) v[r] = s[ph(t + 64 * r)];
    twid<DIR, 8>(v, (float)t * (1.0f / 512.0f));
    dft8<DIR>(v);  // stage 3, Ns=64 (gather == scatter)
}

// ---------------- K1: pack + FFT256 over n1 + w_N twiddle ----------------
// Block: 512 threads = 32 t (FFT lanes) x 16 c (n2 columns). grid (32, 129).
__global__ __launch_bounds__(512) void k_stageA(const float* __restrict__ x,
                                                const float* __restrict__ filt,
                                                float2* __restrict__ U) {
    __shared__ float2 sm[256][16];
    int tx = threadIdx.x;
    int c = tx & 15, t = tx >> 4;
    int n2 = (blockIdx.x << 4) + c;
    int row = blockIdx.y;
    float2 v[8];
    if (row < PAIRS) {
        const float* xa = x + (size_t)row * T_LEN;
        const float* xb = x + (size_t)(row + PAIRS) * T_LEN;
#pragma unroll
        for (int r = 0; r < 4; r++) {
            int n = ((t + 32 * r) << 9) + n2;  // n1 < 128 -> real data
            v[r] = make_float2(__ldg(xa + n), __ldg(xb + n));
        }
    } else {
#pragma unroll
        for (int r = 0; r < 4; r++) {
            int n = ((t + 32 * r) << 9) + n2;
            v[r] = make_float2(__ldg(filt + n), 0.0f);
        }
    }
#pragma unroll
    for (int r = 4; r < 8; r++) v[r] = make_float2(0.0f, 0.0f);

    dft8<-1>(v);  // stage 1 (Ns=1)
#pragma unroll
    for (int r = 0; r < 8; r++) sm[8 * t + r][c] = v[r];
    __syncthreads();
#pragma unroll
    for (int r = 0; r < 8; r++) v[r] = sm[t + 32 * r][c];
    twid<-1, 8>(v, (float)(t & 7) * (1.0f / 64.0f));
    dft8<-1>(v);  // stage 2 (Ns=8)
    __syncthreads();
    {
        int base = ((t >> 3) << 6) + (t & 7);
#pragma unroll
        for (int r = 0; r < 8; r++) sm[base + 8 * r][c] = v[r];
    }
    __syncthreads();

    // stage 3: radix-4, Ns=64; outputs k1 = j + 64m; fuse w_N^{-n2*k1}
    float s64, c64;
    __sincosf(-(TWO_PI / 2048.0f) * (float)n2, &s64, &c64);  // w_N^{-64 n2}
    float2 w64 = make_float2(c64, s64);
    float2* Ur = U + (size_t)row * N_FFT;
#pragma unroll
    for (int g = 0; g < 2; g++) {
        int j = t + 32 * g;
        float2 q[4];
#pragma unroll
        for (int m = 0; m < 4; m++) q[m] = sm[j + 64 * m][c];
        twid<-1, 4>(q, (float)j * (1.0f / 256.0f));
        dft4<-1>(q);
        float sb, cb;
        __sincosf(-(TWO_PI / (float)N_FFT) * (float)(n2 * j), &sb, &cb);
        float2 wk = make_float2(cb, sb);
#pragma unroll
        for (int m = 0; m < 4; m++) {
            int k1 = j + 64 * m;
            Ur[(k1 << 9) + n2] = cmul(q[m], wk);
            wk = cmul(wk, w64);
        }
    }
}

// ---------------- K2f: filter spectrum (row 128), scaled by 1/N ----------------
__global__ __launch_bounds__(512) void k_filter_spec(const float2* __restrict__ U,
                                                     float2* __restrict__ F) {
    __shared__ float2 smem[8][576];
    int tx = threadIdx.x;
    int t = tx & 63, f = tx >> 6;
    int k1 = (blockIdx.x << 3) + f;
    const float2* u = U + (size_t)PAIRS * N_FFT + (k1 << 9);
    float2* s = smem[f];
    float2 v[8];
#pragma unroll
    for (int r = 0; r < 8; r++) v[r] = u[t + 64 * r];
    fft512<-1>(v, s, t);
    float2* Fr = F + (k1 << 9);
#pragma unroll
    for (int r = 0; r < 8; r++) Fr[t + 64 * r] = make_float2(v[r].x * INV_N, v[r].y * INV_N);
}

// ---------------- K23: FFT512 fwd + multiply + IFFT512 + w_N^{+n2 k1}, in place ----------------
// Block: 512 threads = 8 FFT rows (k1) x 64 lanes. grid (32, 128).
__global__ __launch_bounds__(512) void k_stageB_conv(float2* U, const float2* __restrict__ F) {
    __shared__ float2 smem[8][576];
    int tx = threadIdx.x;
    int t = tx & 63, f = tx >> 6;
    int k1 = (blockIdx.x << 3) + f;
    int row = blockIdx.y;
    float2* u = U + (size_t)row * N_FFT + (k1 << 9);
    float2* s = smem[f];
    float2 v[8];
#pragma unroll
    for (int r = 0; r < 8; r++) v[r] = u[t + 64 * r];
    fft512<-1>(v, s, t);
    // spectrum in regs at k2 = t + 64r == inverse stage-1 gather; multiply by filter
    const float2* Fr = F + (k1 << 9);
#pragma unroll
    for (int r = 0; r < 8; r++) v[r] = cmul(v[r], __ldg(Fr + t + 64 * r));
    __syncthreads();  // smem handoff fwd -> inv
    fft512<1>(v, s, t);
    // conj twiddle w_N^{+n2 k1}, n2 = t + 64r
    float sb, cb, ss, cs;
    __sincosf((TWO_PI / (float)N_FFT) * (float)(t * k1), &sb, &cb);
    __sincosf((TWO_PI / 2048.0f) * (float)k1, &ss, &cs);  // w_N^{+64 k1}
    float2 wk = make_float2(cb, sb), wstep = make_float2(cs, ss);
#pragma unroll
    for (int r = 0; r < 8; r++) {
        u[t + 64 * r] = cmul(v[r], wk);
        wk = cmul(wk, wstep);
    }
}

// ---------------- K4: IFFT256 over k1 + causal unpack ----------------
// Block: 512 threads = 32 t x 16 c (n2 columns). grid (32, 128).
__global__ __launch_bounds__(512) void k_stageAinv(const float2* __restrict__ U,
                                                   float* __restrict__ y) {
    __shared__ float2 sm[256][16];
    int tx = threadIdx.x;
    int c = tx & 15, t = tx >> 4;
    int n2 = (blockIdx.x << 4) + c;
    int row = blockIdx.y;
    const float2* u = U + (size_t)row * N_FFT + n2;
    float2 v[8];
#pragma unroll
    for (int r = 0; r < 8; r++) v[r] = __ldg(u + (size_t)((t + 32 * r) << 9));
    dft8<1>(v);  // stage 1 (Ns=1)
#pragma unroll
    for (int r = 0; r < 8; r++) sm[8 * t + r][c] = v[r];
    __syncthreads();
#pragma unroll
    for (int r = 0; r < 8; r++) v[r] = sm[t + 32 * r][c];
    twid<1, 8>(v, (float)(t & 7) * (1.0f / 64.0f));
    dft8<1>(v);  // stage 2 (Ns=8)
    __syncthreads();
    {
        int base = ((t >> 3) << 6) + (t & 7);
#pragma unroll
        for (int r = 0; r < 8; r++) sm[base + 8 * r][c] = v[r];
    }
    __syncthreads();

    float* ya = y + (size_t)row * T_LEN;
    float* yb = y + (size_t)(row + PAIRS) * T_LEN;
#pragma unroll
    for (int g = 0; g < 2; g++) {
        int j = t + 32 * g;
        float2 q[4];
#pragma unroll
        for (int m = 0; m < 4; m++) q[m] = sm[j + 64 * m][c];
        twid<1, 4>(q, (float)j * (1.0f / 256.0f));
        dft4<1>(q);
        // outputs n1 = j + 64m; keep n = 512*n1 + n2 < T  =>  m < 2
#pragma unroll
        for (int m = 0; m < 2; m++) {
            int n = ((j + 64 * m) << 9) + n2;
            ya[n] = q[m].x;
            yb[n] = q[m].y;
        }
    }
}

extern "C" void kernel_launch(void* const* d_in, const int* in_sizes, int n_in,
                              void* d_out, int out_size) {
    const float* x = (const float*)d_in[0];
    const float* filt = (const float*)d_in[1];
    float* y = (float*)d_out;

    float2* U = nullptr;
    float2* F = nullptr;
    cudaGetSymbolAddress((void**)&U, g_buf);
    cudaGetSymbolAddress((void**)&F, g_fspec);

    k_stageA<<<dim3(32, ROWS_F), 512>>>(x, filt, U);
    k_filter_spec<<<32, 512>>>(U, F);
    k_stageB_conv<<<dim3(32, PAIRS), 512>>>(U, F);
    k_stageAinv<<<dim3(32, PAIRS), 512>>>(U, y);
}

// round 3
// speedup vs baseline: 2.5561x; 1.1855x over previous
#include <cuda_runtime.h>

// EpochedFutureFill == causal FIR conv, B=256, T=L=65536, via FFT of N=131072.
// Four-step decomposition: N = 256 (n1, stride 512) x 512 (n2, contiguous).
//   K0 : build twiddle tables (t64, t512, t256) with sincospif
//   K1 : pack + FFT256 over n1 (strided) + w_N^{-n2 k1}  -> U[k1][n2]
//   K2f: filter row: FFT512 over n2 -> F (scaled by 1/N)
//   K23: FFT512 fwd over n2, multiply by F, IFFT512, w_N^{+n2 k1}  (in place)
//   K4 : IFFT256 over k1 (strided) + causal unpack to y
// Real-pair packing: rows (b, b+128) as one complex row; filter real => no unpack.
// Stage twiddles come from tables (forward sign); inverse uses conjugate-multiply.

namespace {
constexpr int N_FFT = 131072;
constexpr int T_LEN = 65536;
constexpr int PAIRS = 128;
constexpr int ROWS_F = 129;
constexpr float TWO_PI = 6.28318530717958647692f;
constexpr float INV_N = 1.0f / (float)N_FFT;
}

// Scratch (no cudaMalloc allowed): 135 MB intermediate + 1 MB filter spectrum.
__device__ float2 g_buf[(size_t)ROWS_F * N_FFT];
__device__ float2 g_fspec[N_FFT];
// Twiddle tables (forward direction: exp(-2*pi*i * ...)).
__device__ float2 g_t64[8 * 8];     // [r][t&7]  : exp(-2pi i * r*(t&7)/64)
__device__ float2 g_t512[8 * 64];   // [r][t]    : exp(-2pi i * r*t/512)
__device__ float2 g_t256[4 * 64];   // [m][j]    : exp(-2pi i * m*j/256)

__device__ __forceinline__ float2 cadd(float2 a, float2 b) { return make_float2(a.x + b.x, a.y + b.y); }
__device__ __forceinline__ float2 csub(float2 a, float2 b) { return make_float2(a.x - b.x, a.y - b.y); }
__device__ __forceinline__ float2 cmul(float2 a, float2 b) {
    return make_float2(fmaf(a.x, b.x, -a.y * b.y), fmaf(a.x, b.y, a.y * b.x));
}
__device__ __forceinline__ float2 cmulc(float2 a, float2 b) {  // a * conj(b)
    return make_float2(fmaf(a.x, b.x, a.y * b.y), fmaf(a.y, b.x, -a.x * b.y));
}
template <int DIR>
__device__ __forceinline__ float2 twmul(float2 a, float2 w) {  // tables are forward
    return (DIR < 0) ? cmul(a, w) : cmulc(a, w);
}
template <int DIR>
__device__ __forceinline__ float2 cmuli(float2 a) {  // * (i*DIR)
    return (DIR < 0) ? make_float2(a.y, -a.x) : make_float2(-a.y, a.x);
}

template <int DIR>
__device__ __forceinline__ void dft4(float2 v[4]) {
    float2 t0 = cadd(v[0], v[2]);
    float2 t1 = cadd(v[1], v[3]);
    float2 t2 = csub(v[0], v[2]);
    float2 t3 = cmuli<DIR>(csub(v[1], v[3]));
    v[0] = cadd(t0, t1);
    v[2] = csub(t0, t1);
    v[1] = cadd(t2, t3);
    v[3] = csub(t2, t3);
}

template <int DIR>
__device__ __forceinline__ void dft8(float2 v[8]) {
    const float C = 0.70710678118654752440f;
    float2 b[4], d[4];
#pragma unroll
    for (int i = 0; i < 4; i++) {
        b[i] = cadd(v[i], v[i + 4]);
        d[i] = csub(v[i], v[i + 4]);
    }
    d[1] = cmul(d[1], make_float2(C, (float)DIR * C));
    d[2] = cmuli<DIR>(d[2]);
    d[3] = cmul(d[3], make_float2(-C, (float)DIR * C));
    dft4<DIR>(b);
    dft4<DIR>(d);
    v[0] = b[0]; v[2] = b[1]; v[4] = b[2]; v[6] = b[3];
    v[1] = d[0]; v[3] = d[1]; v[5] = d[2]; v[7] = d[3];
}

// ---------------- K0: build twiddle tables (512 threads, 1 block) ----------------
__global__ void k_init_tables() {
    int i = threadIdx.x;
    {   // t512: r = i>>6, t = i&63
        int r = i >> 6, t = i & 63;
        float s, c;
        sincospif(-2.0f * (float)(r * t) / 512.0f, &s, &c);
        g_t512[i] = make_float2(c, s);
    }
    if (i < 64) {  // t64: r = i>>3, u = i&7
        int r = i >> 3, u = i & 7;
        float s, c;
        sincospif(-2.0f * (float)(r * u) / 64.0f, &s, &c);
        g_t64[i] = make_float2(c, s);
    }
    if (i < 256) {  // t256: m = i>>6, j = i&63
        int m = i >> 6, j = i & 63;
        float s, c;
        sincospif(-2.0f * (float)(m * j) / 256.0f, &s, &c);
        g_t256[i] = make_float2(c, s);
    }
}

// smem swizzle for the contiguous-dim 512 FFT (conflict-free scatters)
__device__ __forceinline__ int ph(int n) { return n + (n >> 3); }

// Full 512-pt FFT for one row held by 64 threads (t in [0,64)), 8 values each.
// Entry: v[r] = data[t + 64*r]. Exit: v[r] = DFT[t + 64*r]. s = per-FFT smem (576 float2).
template <int DIR>
__device__ __forceinline__ void fft512(float2* v, float2* s, int t) {
    dft8<DIR>(v);  // stage 1, Ns=1
#pragma unroll
    for (int r = 0; r < 8; r++) s[ph(8 * t + r)] = v[r];
    __syncthreads();
#pragma unroll
    for (int r = 0; r < 8; r++) v[r] = s[ph(t + 64 * r)];
    {
        int t8 = t & 7;
#pragma unroll
        for (int r = 1; r < 8; r++) v[r] = twmul<DIR>(v[r], __ldg(&g_t64[r * 8 + t8]));
    }
    dft8<DIR>(v);  // stage 2, Ns=8
    __syncthreads();
    {
        int base = ((t >> 3) << 6) + (t & 7);
#pragma unroll
        for (int r = 0; r < 8; r++) s[ph(base + 8 * r)] = v[r];
    }
    __syncthreads();
#pragma unroll
    for (int r = 0; r < 8; r++) v[r] = s[ph(t + 64 * r)];
#pragma unroll
    for (int r = 1; r < 8; r++) v[r] = twmul<DIR>(v[r], __ldg(&g_t512[r * 64 + t]));
    dft8<DIR>(v);  // stage 3, Ns=64 (gather == scatter)
}

// ---------------- K1: pack + FFT256 over n1 + w_N twiddle ----------------
// Block: 512 threads = 32 t (FFT lanes) x 16 c (n2 columns). grid (32, 129).
__global__ __launch_bounds__(512) void k_stageA(const float* __restrict__ x,
                                                const float* __restrict__ filt,
                                                float2* __restrict__ U) {
    __shared__ float2 sm[256][16];
    int tx = threadIdx.x;
    int c = tx & 15, t = tx >> 4;
    int n2 = (blockIdx.x << 4) + c;
    int row = blockIdx.y;
    float2 v[8];
    if (row < PAIRS) {
        const float* xa = x + (size_t)row * T_LEN;
        const float* xb = x + (size_t)(row + PAIRS) * T_LEN;
#pragma unroll
        for (int r = 0; r < 4; r++) {
            int n = ((t + 32 * r) << 9) + n2;  // n1 < 128 -> real data
            v[r] = make_float2(__ldg(xa + n), __ldg(xb + n));
        }
    } else {
#pragma unroll
        for (int r = 0; r < 4; r++) {
            int n = ((t + 32 * r) << 9) + n2;
            v[r] = make_float2(__ldg(filt + n), 0.0f);
        }
    }
#pragma unroll
    for (int r = 4; r < 8; r++) v[r] = make_float2(0.0f, 0.0f);

    dft8<-1>(v);  // stage 1 (Ns=1)
#pragma unroll
    for (int r = 0; r < 8; r++) sm[8 * t + r][c] = v[r];
    __syncthreads();
#pragma unroll
    for (int r = 0; r < 8; r++) v[r] = sm[t + 32 * r][c];
    {
        int t8 = t & 7;
#pragma unroll
        for (int r = 1; r < 8; r++) v[r] = cmul(v[r], __ldg(&g_t64[r * 8 + t8]));
    }
    dft8<-1>(v);  // stage 2 (Ns=8)
    __syncthreads();
    {
        int base = ((t >> 3) << 6) + (t & 7);
#pragma unroll
        for (int r = 0; r < 8; r++) sm[base + 8 * r][c] = v[r];
    }
    __syncthreads();

    // stage 3: radix-4, Ns=64; outputs k1 = j + 64m; fuse w_N^{-n2*k1}
    float s64, c64;
    __sincosf(-(TWO_PI / 2048.0f) * (float)n2, &s64, &c64);  // w_N^{-64 n2}
    float2 w64 = make_float2(c64, s64);
    float2* Ur = U + (size_t)row * N_FFT;
#pragma unroll
    for (int g = 0; g < 2; g++) {
        int j = t + 32 * g;
        float2 q[4];
#pragma unroll
        for (int m = 0; m < 4; m++) q[m] = sm[j + 64 * m][c];
#pragma unroll
        for (int m = 1; m < 4; m++) q[m] = cmul(q[m], __ldg(&g_t256[m * 64 + j]));
        dft4<-1>(q);
        float sb, cb;
        __sincosf(-(TWO_PI / (float)N_FFT) * (float)(n2 * j), &sb, &cb);
        float2 wk = make_float2(cb, sb);
#pragma unroll
        for (int m = 0; m < 4; m++) {
            int k1 = j + 64 * m;
            Ur[(k1 << 9) + n2] = cmul(q[m], wk);
            wk = cmul(wk, w64);
        }
    }
}

// ---------------- K2f: filter spectrum (row 128), scaled by 1/N ----------------
__global__ __launch_bounds__(512) void k_filter_spec(const float2* __restrict__ U,
                                                     float2* __restrict__ F) {
    __shared__ float2 smem[8][576];
    int tx = threadIdx.x;
    int t = tx & 63, f = tx >> 6;
    int k1 = (blockIdx.x << 3) + f;
    const float2* u = U + (size_t)PAIRS * N_FFT + (k1 << 9);
    float2* s = smem[f];
    float2 v[8];
#pragma unroll
    for (int r = 0; r < 8; r++) v[r] = u[t + 64 * r];
    fft512<-1>(v, s, t);
    float2* Fr = F + (k1 << 9);
#pragma unroll
    for (int r = 0; r < 8; r++) Fr[t + 64 * r] = make_float2(v[r].x * INV_N, v[r].y * INV_N);
}

// ---------------- K23: FFT512 fwd + multiply + IFFT512 + w_N^{+n2 k1}, in place ----------------
// Block: 512 threads = 8 FFT rows (k1) x 64 lanes. grid (32, 128).
__global__ __launch_bounds__(512) void k_stageB_conv(float2* U, const float2* __restrict__ F) {
    __shared__ float2 smem[8][576];
    int tx = threadIdx.x;
    int t = tx & 63, f = tx >> 6;
    int k1 = (blockIdx.x << 3) + f;
    int row = blockIdx.y;
    float2* u = U + (size_t)row * N_FFT + (k1 << 9);
    float2* s = smem[f];
    float2 v[8];
#pragma unroll
    for (int r = 0; r < 8; r++) v[r] = u[t + 64 * r];
    fft512<-1>(v, s, t);
    // spectrum in regs at k2 = t + 64r == inverse stage-1 gather; multiply by filter
    const float2* Fr = F + (k1 << 9);
#pragma unroll
    for (int r = 0; r < 8; r++) v[r] = cmul(v[r], __ldg(Fr + t + 64 * r));
    __syncthreads();  // smem handoff fwd -> inv
    fft512<1>(v, s, t);
    // conj twiddle w_N^{+n2 k1}, n2 = t + 64r
    float sb, cb, ss, cs;
    __sincosf((TWO_PI / (float)N_FFT) * (float)(t * k1), &sb, &cb);
    __sincosf((TWO_PI / 2048.0f) * (float)k1, &ss, &cs);  // w_N^{+64 k1}
    float2 wk = make_float2(cb, sb), wstep = make_float2(cs, ss);
#pragma unroll
    for (int r = 0; r < 8; r++) {
        u[t + 64 * r] = cmul(v[r], wk);
        wk = cmul(wk, wstep);
    }
}

// ---------------- K4: IFFT256 over k1 + causal unpack ----------------
// Block: 512 threads = 32 t x 16 c (n2 columns). grid (32, 128).
__global__ __launch_bounds__(512) void k_stageAinv(const float2* __restrict__ U,
                                                   float* __restrict__ y) {
    __shared__ float2 sm[256][16];
    int tx = threadIdx.x;
    int c = tx & 15, t = tx >> 4;
    int n2 = (blockIdx.x << 4) + c;
    int row = blockIdx.y;
    const float2* u = U + (size_t)row * N_FFT + n2;
    float2 v[8];
#pragma unroll
    for (int r = 0; r < 8; r++) v[r] = __ldg(u + (size_t)((t + 32 * r) << 9));
    dft8<1>(v);  // stage 1 (Ns=1)
#pragma unroll
    for (int r = 0; r < 8; r++) sm[8 * t + r][c] = v[r];
    __syncthreads();
#pragma unroll
    for (int r = 0; r < 8; r++) v[r] = sm[t + 32 * r][c];
    {
        int t8 = t & 7;
#pragma unroll
        for (int r = 1; r < 8; r++) v[r] = cmulc(v[r], __ldg(&g_t64[r * 8 + t8]));
    }
    dft8<1>(v);  // stage 2 (Ns=8)
    __syncthreads();
    {
        int base = ((t >> 3) << 6) + (t & 7);
#pragma unroll
        for (int r = 0; r < 8; r++) sm[base + 8 * r][c] = v[r];
    }
    __syncthreads();

    float* ya = y + (size_t)row * T_LEN;
    float* yb = y + (size_t)(row + PAIRS) * T_LEN;
#pragma unroll
    for (int g = 0; g < 2; g++) {
        int j = t + 32 * g;
        float2 q[4];
#pragma unroll
        for (int m = 0; m < 4; m++) q[m] = sm[j + 64 * m][c];
#pragma unroll
        for (int m = 1; m < 4; m++) q[m] = cmulc(q[m], __ldg(&g_t256[m * 64 + j]));
        dft4<1>(q);
        // outputs n1 = j + 64m; keep n = 512*n1 + n2 < T  =>  m < 2
#pragma unroll
        for (int m = 0; m < 2; m++) {
            int n = ((j + 64 * m) << 9) + n2;
            ya[n] = q[m].x;
            yb[n] = q[m].y;
        }
    }
}

extern "C" void kernel_launch(void* const* d_in, const int* in_sizes, int n_in,
                              void* d_out, int out_size) {
    const float* x = (const float*)d_in[0];
    const float* filt = (const float*)d_in[1];
    float* y = (float*)d_out;

    float2* U = nullptr;
    float2* F = nullptr;
    cudaGetSymbolAddress((void**)&U, g_buf);
    cudaGetSymbolAddress((void**)&F, g_fspec);

    k_init_tables<<<1, 512>>>();
    k_stageA<<<dim3(32, ROWS_F), 512>>>(x, filt, U);
    k_filter_spec<<<32, 512>>>(U, F);
    k_stageB_conv<<<dim3(32, PAIRS), 512>>>(U, F);
    k_stageAinv<<<dim3(32, PAIRS), 512>>>(U, y);
}

// round 4
// speedup vs baseline: 2.9146x; 1.1403x over previous
#include <cuda_runtime.h>

// EpochedFutureFill == causal FIR conv, B=256, T=L=65536, via FFT of N=131072.
// Four-step decomposition: N = 256 (n1, stride 512) x 512 (n2, contiguous).
//   K0 : build twiddle tables (t64, t512, t256) with sincospif
//   K1 : pack + FFT256 over n1 (strided) + w_N^{-n2 k1}  -> U[k1][n2]
//   K2f: filter row: FFT512 over n2 -> F (scaled by 1/N)
//   K23: FFT512 fwd over n2, multiply by F, IFFT512, w_N^{+n2 k1}  (in place)
//   K4 : IFFT256 over k1 (strided) + causal unpack to y
// Real-pair packing: rows (b, b+128) as one complex row; filter real => no unpack.
// K23/K2f use per-FFT named barriers (2 warps per FFT) + launch_bounds(512,2).

namespace {
constexpr int N_FFT = 131072;
constexpr int T_LEN = 65536;
constexpr int PAIRS = 128;
constexpr int ROWS_F = 129;
constexpr float TWO_PI = 6.28318530717958647692f;
constexpr float INV_N = 1.0f / (float)N_FFT;
}

// Scratch (no cudaMalloc allowed): 135 MB intermediate + 1 MB filter spectrum.
__device__ float2 g_buf[(size_t)ROWS_F * N_FFT];
__device__ float2 g_fspec[N_FFT];
// Twiddle tables (forward direction: exp(-2*pi*i * ...)).
__device__ float2 g_t64[8 * 8];     // [r][t&7]  : exp(-2pi i * r*(t&7)/64)
__device__ float2 g_t512[8 * 64];   // [r][t]    : exp(-2pi i * r*t/512)
__device__ float2 g_t256[4 * 64];   // [m][j]    : exp(-2pi i * m*j/256)

__device__ __forceinline__ float2 cadd(float2 a, float2 b) { return make_float2(a.x + b.x, a.y + b.y); }
__device__ __forceinline__ float2 csub(float2 a, float2 b) { return make_float2(a.x - b.x, a.y - b.y); }
__device__ __forceinline__ float2 cmul(float2 a, float2 b) {
    return make_float2(fmaf(a.x, b.x, -a.y * b.y), fmaf(a.x, b.y, a.y * b.x));
}
__device__ __forceinline__ float2 cmulc(float2 a, float2 b) {  // a * conj(b)
    return make_float2(fmaf(a.x, b.x, a.y * b.y), fmaf(a.y, b.x, -a.x * b.y));
}
template <int DIR>
__device__ __forceinline__ float2 twmul(float2 a, float2 w) {  // tables are forward
    return (DIR < 0) ? cmul(a, w) : cmulc(a, w);
}
template <int DIR>
__device__ __forceinline__ float2 cmuli(float2 a) {  // * (i*DIR)
    return (DIR < 0) ? make_float2(a.y, -a.x) : make_float2(-a.y, a.x);
}

// 2-warp named barrier: syncs the 64 threads owning one 512-pt FFT.
__device__ __forceinline__ void barx(int id) {
    asm volatile("bar.sync %0, 64;" :: "r"(id) : "memory");
}

template <int DIR>
__device__ __forceinline__ void dft4(float2 v[4]) {
    float2 t0 = cadd(v[0], v[2]);
    float2 t1 = cadd(v[1], v[3]);
    float2 t2 = csub(v[0], v[2]);
    float2 t3 = cmuli<DIR>(csub(v[1], v[3]));
    v[0] = cadd(t0, t1);
    v[2] = csub(t0, t1);
    v[1] = cadd(t2, t3);
    v[3] = csub(t2, t3);
}

template <int DIR>
__device__ __forceinline__ void dft8(float2 v[8]) {
    const float C = 0.70710678118654752440f;
    float2 b[4], d[4];
#pragma unroll
    for (int i = 0; i < 4; i++) {
        b[i] = cadd(v[i], v[i + 4]);
        d[i] = csub(v[i], v[i + 4]);
    }
    d[1] = cmul(d[1], make_float2(C, (float)DIR * C));
    d[2] = cmuli<DIR>(d[2]);
    d[3] = cmul(d[3], make_float2(-C, (float)DIR * C));
    dft4<DIR>(b);
    dft4<DIR>(d);
    v[0] = b[0]; v[2] = b[1]; v[4] = b[2]; v[6] = b[3];
    v[1] = d[0]; v[3] = d[1]; v[5] = d[2]; v[7] = d[3];
}

// ---------------- K0: build twiddle tables (512 threads, 1 block) ----------------
__global__ void k_init_tables() {
    int i = threadIdx.x;
    {   // t512: r = i>>6, t = i&63
        int r = i >> 6, t = i & 63;
        float s, c;
        sincospif(-2.0f * (float)(r * t) / 512.0f, &s, &c);
        g_t512[i] = make_float2(c, s);
    }
    if (i < 64) {  // t64: r = i>>3, u = i&7
        int r = i >> 3, u = i & 7;
        float s, c;
        sincospif(-2.0f * (float)(r * u) / 64.0f, &s, &c);
        g_t64[i] = make_float2(c, s);
    }
    if (i < 256) {  // t256: m = i>>6, j = i&63
        int m = i >> 6, j = i & 63;
        float s, c;
        sincospif(-2.0f * (float)(m * j) / 256.0f, &s, &c);
        g_t256[i] = make_float2(c, s);
    }
}

// smem swizzle for the contiguous-dim 512 FFT (conflict-free scatters)
__device__ __forceinline__ int ph(int n) { return n + (n >> 3); }

// Full 512-pt FFT for one row held by 64 threads (t in [0,64)), 8 values each.
// Entry: v[r] = data[t + 64*r]. Exit: v[r] = DFT[t + 64*r]. s = per-FFT smem (576 float2).
// Synchronizes ONLY the 2 warps owning this FFT via named barrier `bar`.
template <int DIR>
__device__ __forceinline__ void fft512(float2* v, float2* s, int t, int bar) {
    dft8<DIR>(v);  // stage 1, Ns=1
#pragma unroll
    for (int r = 0; r < 8; r++) s[ph(8 * t + r)] = v[r];
    barx(bar);
#pragma unroll
    for (int r = 0; r < 8; r++) v[r] = s[ph(t + 64 * r)];
    {
        int t8 = t & 7;
#pragma unroll
        for (int r = 1; r < 8; r++) v[r] = twmul<DIR>(v[r], __ldg(&g_t64[r * 8 + t8]));
    }
    dft8<DIR>(v);  // stage 2, Ns=8
    barx(bar);
    {
        int base = ((t >> 3) << 6) + (t & 7);
#pragma unroll
        for (int r = 0; r < 8; r++) s[ph(base + 8 * r)] = v[r];
    }
    barx(bar);
#pragma unroll
    for (int r = 0; r < 8; r++) v[r] = s[ph(t + 64 * r)];
#pragma unroll
    for (int r = 1; r < 8; r++) v[r] = twmul<DIR>(v[r], __ldg(&g_t512[r * 64 + t]));
    dft8<DIR>(v);  // stage 3, Ns=64 (gather == scatter)
}

// ---------------- K1: pack + FFT256 over n1 + w_N twiddle ----------------
// Block: 512 threads = 32 t (FFT lanes) x 16 c (n2 columns). grid (32, 129).
__global__ __launch_bounds__(512) void k_stageA(const float* __restrict__ x,
                                                const float* __restrict__ filt,
                                                float2* __restrict__ U) {
    __shared__ float2 sm[256][16];
    int tx = threadIdx.x;
    int c = tx & 15, t = tx >> 4;
    int n2 = (blockIdx.x << 4) + c;
    int row = blockIdx.y;
    float2 v[8];
    if (row < PAIRS) {
        const float* xa = x + (size_t)row * T_LEN;
        const float* xb = x + (size_t)(row + PAIRS) * T_LEN;
#pragma unroll
        for (int r = 0; r < 4; r++) {
            int n = ((t + 32 * r) << 9) + n2;  // n1 < 128 -> real data
            v[r] = make_float2(__ldg(xa + n), __ldg(xb + n));
        }
    } else {
#pragma unroll
        for (int r = 0; r < 4; r++) {
            int n = ((t + 32 * r) << 9) + n2;
            v[r] = make_float2(__ldg(filt + n), 0.0f);
        }
    }
#pragma unroll
    for (int r = 4; r < 8; r++) v[r] = make_float2(0.0f, 0.0f);

    dft8<-1>(v);  // stage 1 (Ns=1)
#pragma unroll
    for (int r = 0; r < 8; r++) sm[8 * t + r][c] = v[r];
    __syncthreads();
#pragma unroll
    for (int r = 0; r < 8; r++) v[r] = sm[t + 32 * r][c];
    {
        int t8 = t & 7;
#pragma unroll
        for (int r = 1; r < 8; r++) v[r] = cmul(v[r], __ldg(&g_t64[r * 8 + t8]));
    }
    dft8<-1>(v);  // stage 2 (Ns=8)
    __syncthreads();
    {
        int base = ((t >> 3) << 6) + (t & 7);
#pragma unroll
        for (int r = 0; r < 8; r++) sm[base + 8 * r][c] = v[r];
    }
    __syncthreads();

    // stage 3: radix-4, Ns=64; outputs k1 = j + 64m; fuse w_N^{-n2*k1}
    float s64, c64;
    __sincosf(-(TWO_PI / 2048.0f) * (float)n2, &s64, &c64);  // w_N^{-64 n2}
    float2 w64 = make_float2(c64, s64);
    float2* Ur = U + (size_t)row * N_FFT;
#pragma unroll
    for (int g = 0; g < 2; g++) {
        int j = t + 32 * g;
        float2 q[4];
#pragma unroll
        for (int m = 0; m < 4; m++) q[m] = sm[j + 64 * m][c];
#pragma unroll
        for (int m = 1; m < 4; m++) q[m] = cmul(q[m], __ldg(&g_t256[m * 64 + j]));
        dft4<-1>(q);
        float sb, cb;
        __sincosf(-(TWO_PI / (float)N_FFT) * (float)(n2 * j), &sb, &cb);
        float2 wk = make_float2(cb, sb);
#pragma unroll
        for (int m = 0; m < 4; m++) {
            int k1 = j + 64 * m;
            Ur[(k1 << 9) + n2] = cmul(q[m], wk);
            wk = cmul(wk, w64);
        }
    }
}

// ---------------- K2f: filter spectrum (row 128), scaled by 1/N ----------------
__global__ __launch_bounds__(512, 2) void k_filter_spec(const float2* __restrict__ U,
                                                        float2* __restrict__ F) {
    __shared__ float2 smem[8][576];
    int tx = threadIdx.x;
    int t = tx & 63, f = tx >> 6;
    int k1 = (blockIdx.x << 3) + f;
    const float2* u = U + (size_t)PAIRS * N_FFT + (k1 << 9);
    float2* s = smem[f];
    float2 v[8];
#pragma unroll
    for (int r = 0; r < 8; r++) v[r] = u[t + 64 * r];
    fft512<-1>(v, s, t, f + 1);
    float2* Fr = F + (k1 << 9);
#pragma unroll
    for (int r = 0; r < 8; r++) Fr[t + 64 * r] = make_float2(v[r].x * INV_N, v[r].y * INV_N);
}

// ---------------- K23: FFT512 fwd + multiply + IFFT512 + w_N^{+n2 k1}, in place ----------------
// Block: 512 threads = 8 FFT rows (k1) x 64 lanes. grid (32, 128).
// Per-FFT named barriers + forced 2 blocks/SM for occupancy.
__global__ __launch_bounds__(512, 2) void k_stageB_conv(float2* U, const float2* __restrict__ F) {
    __shared__ float2 smem[8][576];
    int tx = threadIdx.x;
    int t = tx & 63, f = tx >> 6;
    int k1 = (blockIdx.x << 3) + f;
    int row = blockIdx.y;
    float2* u = U + (size_t)row * N_FFT + (k1 << 9);
    float2* s = smem[f];
    int bar = f + 1;
    float2 v[8];
#pragma unroll
    for (int r = 0; r < 8; r++) v[r] = u[t + 64 * r];
    fft512<-1>(v, s, t, bar);
    // spectrum in regs at k2 = t + 64r == inverse stage-1 gather; multiply by filter
    const float2* Fr = F + (k1 << 9);
#pragma unroll
    for (int r = 0; r < 8; r++) v[r] = cmul(v[r], __ldg(Fr + t + 64 * r));
    barx(bar);  // smem handoff fwd -> inv (2-warp scope)
    fft512<1>(v, s, t, bar);
    // conj twiddle w_N^{+n2 k1}, n2 = t + 64r
    float sb, cb, ss, cs;
    __sincosf((TWO_PI / (float)N_FFT) * (float)(t * k1), &sb, &cb);
    __sincosf((TWO_PI / 2048.0f) * (float)k1, &ss, &cs);  // w_N^{+64 k1}
    float2 wk = make_float2(cb, sb), wstep = make_float2(cs, ss);
#pragma unroll
    for (int r = 0; r < 8; r++) {
        u[t + 64 * r] = cmul(v[r], wk);
        wk = cmul(wk, wstep);
    }
}

// ---------------- K4: IFFT256 over k1 + causal unpack ----------------
// Block: 512 threads = 32 t x 16 c (n2 columns). grid (32, 128).
__global__ __launch_bounds__(512) void k_stageAinv(const float2* __restrict__ U,
                                                   float* __restrict__ y) {
    __shared__ float2 sm[256][16];
    int tx = threadIdx.x;
    int c = tx & 15, t = tx >> 4;
    int n2 = (blockIdx.x << 4) + c;
    int row = blockIdx.y;
    const float2* u = U + (size_t)row * N_FFT + n2;
    float2 v[8];
#pragma unroll
    for (int r = 0; r < 8; r++) v[r] = __ldg(u + (size_t)((t + 32 * r) << 9));
    dft8<1>(v);  // stage 1 (Ns=1)
#pragma unroll
    for (int r = 0; r < 8; r++) sm[8 * t + r][c] = v[r];
    __syncthreads();
#pragma unroll
    for (int r = 0; r < 8; r++) v[r] = sm[t + 32 * r][c];
    {
        int t8 = t & 7;
#pragma unroll
        for (int r = 1; r < 8; r++) v[r] = cmulc(v[r], __ldg(&g_t64[r * 8 + t8]));
    }
    dft8<1>(v);  // stage 2 (Ns=8)
    __syncthreads();
    {
        int base = ((t >> 3) << 6) + (t & 7);
#pragma unroll
        for (int r = 0; r < 8; r++) sm[base + 8 * r][c] = v[r];
    }
    __syncthreads();

    float* ya = y + (size_t)row * T_LEN;
    float* yb = y + (size_t)(row + PAIRS) * T_LEN;
#pragma unroll
    for (int g = 0; g < 2; g++) {
        int j = t + 32 * g;
        float2 q[4];
#pragma unroll
        for (int m = 0; m < 4; m++) q[m] = sm[j + 64 * m][c];
#pragma unroll
        for (int m = 1; m < 4; m++) q[m] = cmulc(q[m], __ldg(&g_t256[m * 64 + j]));
        dft4<1>(q);
        // outputs n1 = j + 64m; keep n = 512*n1 + n2 < T  =>  m < 2
#pragma unroll
        for (int m = 0; m < 2; m++) {
            int n = ((j + 64 * m) << 9) + n2;
            ya[n] = q[m].x;
            yb[n] = q[m].y;
        }
    }
}

extern "C" void kernel_launch(void* const* d_in, const int* in_sizes, int n_in,
                              void* d_out, int out_size) {
    const float* x = (const float*)d_in[0];
    const float* filt = (const float*)d_in[1];
    float* y = (float*)d_out;

    float2* U = nullptr;
    float2* F = nullptr;
    cudaGetSymbolAddress((void**)&U, g_buf);
    cudaGetSymbolAddress((void**)&F, g_fspec);

    k_init_tables<<<1, 512>>>();
    k_stageA<<<dim3(32, ROWS_F), 512>>>(x, filt, U);
    k_filter_spec<<<32, 512>>>(U, F);
    k_stageB_conv<<<dim3(32, PAIRS), 512>>>(U, F);
    k_stageAinv<<<dim3(32, PAIRS), 512>>>(U, y);
}

// round 5
// speedup vs baseline: 2.9526x; 1.0130x over previous
#include <cuda_runtime.h>

// EpochedFutureFill == causal FIR conv, B=256, T=L=65536, via FFT of N=131072.
// Four-step decomposition: N = 256 (n1, stride 512) x 512 (n2, contiguous).
//   K0 : build twiddle tables
//   K1 : pack + FFT256 over n1 (strided) + w_N^{-n2 k1}  -> U[k1][n2]
//   K2f: filter row: warp-FFT512 -> Fperm (permuted per-lane layout, scaled 1/N)
//   K23: warp-autonomous FFT512 fwd + multiply + IFFT512 + w_N^{+n2 k1} (in place)
//   K4 : IFFT256 over k1 (strided) + causal unpack to y
// K23/K2f: one warp per 512-pt FFT, 16 float2 regs/thread, factor 16x32:
//   in-thread DFT16 -> smem transpose (xor swizzle) -> shuffle radix-2 + DFT16.
// Only ONE smem exchange per FFT direction; no block barriers at all.

namespace {
constexpr int N_FFT = 131072;
constexpr int T_LEN = 65536;
constexpr int PAIRS = 128;
constexpr int ROWS_F = 129;
constexpr float TWO_PI = 6.28318530717958647692f;
constexpr float INV_N = 1.0f / (float)N_FFT;
}

// Scratch (no cudaMalloc allowed): 135 MB intermediate + permuted filter spectrum.
__device__ float2 g_buf[(size_t)ROWS_F * N_FFT];
__device__ float2 g_fspec[N_FFT];  // Fperm[k1][q'][lane]
// Twiddle tables (forward direction: exp(-2*pi*i * ...)).
__device__ float2 g_t64[8 * 8];     // [r][t&7]  : exp(-2pi i * r*(t&7)/64)   (K1/K4)
__device__ float2 g_t256[4 * 64];   // [m][j]    : exp(-2pi i * m*j/256)      (K1/K4)
__device__ float2 g_twA[16 * 32];   // [p][t]    : exp(-2pi i * p*t/512)      (warp FFT)
__device__ float2 g_twB[32 * 16];   // [t][p]    : same, transposed           (warp FFT inv)
__device__ float2 g_w32[16];        // [j]       : exp(-2pi i * j/32)

__device__ __forceinline__ float2 cadd(float2 a, float2 b) { return make_float2(a.x + b.x, a.y + b.y); }
__device__ __forceinline__ float2 csub(float2 a, float2 b) { return make_float2(a.x - b.x, a.y - b.y); }
__device__ __forceinline__ float2 cmul(float2 a, float2 b) {
    return make_float2(fmaf(a.x, b.x, -a.y * b.y), fmaf(a.x, b.y, a.y * b.x));
}
__device__ __forceinline__ float2 cmulc(float2 a, float2 b) {  // a * conj(b)
    return make_float2(fmaf(a.x, b.x, a.y * b.y), fmaf(a.y, b.x, -a.x * b.y));
}
template <int DIR>
__device__ __forceinline__ float2 cmuli(float2 a) {  // * (i*DIR)
    return (DIR < 0) ? make_float2(a.y, -a.x) : make_float2(-a.y, a.x);
}

template <int DIR>
__device__ __forceinline__ void dft4(float2 v[4]) {
    float2 t0 = cadd(v[0], v[2]);
    float2 t1 = cadd(v[1], v[3]);
    float2 t2 = csub(v[0], v[2]);
    float2 t3 = cmuli<DIR>(csub(v[1], v[3]));
    v[0] = cadd(t0, t1);
    v[2] = csub(t0, t1);
    v[1] = cadd(t2, t3);
    v[3] = csub(t2, t3);
}

template <int DIR>
__device__ __forceinline__ void dft8(float2 v[8]) {
    const float C = 0.70710678118654752440f;
    float2 b[4], d[4];
#pragma unroll
    for (int i = 0; i < 4; i++) {
        b[i] = cadd(v[i], v[i + 4]);
        d[i] = csub(v[i], v[i + 4]);
    }
    d[1] = cmul(d[1], make_float2(C, (float)DIR * C));
    d[2] = cmuli<DIR>(d[2]);
    d[3] = cmul(d[3], make_float2(-C, (float)DIR * C));
    dft4<DIR>(b);
    dft4<DIR>(d);
    v[0] = b[0]; v[2] = b[1]; v[4] = b[2]; v[6] = b[3];
    v[1] = d[0]; v[3] = d[1]; v[5] = d[2]; v[7] = d[3];
}

// In-thread natural-order 16-pt DFT: out[k] = sum_n in[n] exp(DIR*2pi*i*k*n/16).
// Decompose n = j + 4i: inner DFT4 over i, twiddle w16^{qj}, outer DFT4 over j.
template <int DIR>
__device__ __forceinline__ void dft16(float2 v[16]) {
    const float C1 = 0.92387953251128674f, S1 = 0.38268343236508978f;
    const float C2 = 0.70710678118654752f;
    const float D = (float)DIR;
    float2 g[4][4];
#pragma unroll
    for (int j = 0; j < 4; j++) {
        float2 a[4] = {v[j], v[j + 4], v[j + 8], v[j + 12]};
        dft4<DIR>(a);
#pragma unroll
        for (int q = 0; q < 4; q++) g[j][q] = a[q];
    }
    float2 w1 = make_float2(C1, D * S1), w2 = make_float2(C2, D * C2);
    float2 w3 = make_float2(S1, D * C1), w6 = make_float2(-C2, D * C2);
    float2 w9 = make_float2(-C1, -D * S1);
    g[1][1] = cmul(g[1][1], w1);
    g[1][2] = cmul(g[1][2], w2);
    g[1][3] = cmul(g[1][3], w3);
    g[2][1] = cmul(g[2][1], w2);
    g[2][2] = cmuli<DIR>(g[2][2]);  // w16^4 = DIR*i
    g[2][3] = cmul(g[2][3], w6);
    g[3][1] = cmul(g[3][1], w3);
    g[3][2] = cmul(g[3][2], w6);
    g[3][3] = cmul(g[3][3], w9);
#pragma unroll
    for (int q = 0; q < 4; q++) {
        float2 a[4] = {g[0][q], g[1][q], g[2][q], g[3][q]};
        dft4<DIR>(a);
#pragma unroll
        for (int s = 0; s < 4; s++) v[q + 4 * s] = a[s];
    }
}

__device__ __forceinline__ float2 shflx1(float2 a) {
    return make_float2(__shfl_xor_sync(0xffffffffu, a.x, 1),
                       __shfl_xor_sync(0xffffffffu, a.y, 1));
}

// ---------------- K0: build twiddle tables (512 threads, 1 block) ----------------
__global__ void k_init_tables() {
    int i = threadIdx.x;
    {   // warp-FFT tables: p = i>>5 (0..15), t = i&31
        int p = i >> 5, t = i & 31;
        float s, c;
        sincospif(-2.0f * (float)(p * t) / 512.0f, &s, &c);
        g_twA[p * 32 + t] = make_float2(c, s);
        g_twB[t * 16 + p] = make_float2(c, s);
    }
    if (i < 64) {  // t64: r = i>>3, u = i&7
        int r = i >> 3, u = i & 7;
        float s, c;
        sincospif(-2.0f * (float)(r * u) / 64.0f, &s, &c);
        g_t64[i] = make_float2(c, s);
    }
    if (i < 256) {  // t256: m = i>>6, j = i&63
        int m = i >> 6, j = i & 63;
        float s, c;
        sincospif(-2.0f * (float)(m * j) / 256.0f, &s, &c);
        g_t256[i] = make_float2(c, s);
    }
    if (i < 16) {  // w32
        float s, c;
        sincospif(-2.0f * (float)i / 32.0f, &s, &c);
        g_w32[i] = make_float2(c, s);
    }
}

// ---------------- warp-level 512-pt forward FFT ----------------
// Entry: v[r] = u[lane + 32r]. Exit: lane (p=lane>>1, h=lane&1) holds
// spectrum Y[p + 32*q' + 16*h] in v[q']. sw = 512-float2 warp-private smem.
__device__ __forceinline__ void wfft512_fwd(float2 v[16], float2* sw, int lane) {
    dft16<-1>(v);  // over r (stride-32 samples)
#pragma unroll
    for (int p = 0; p < 16; p++) v[p] = cmul(v[p], __ldg(&g_twA[p * 32 + lane]));
    // transpose: write row t=lane (xor swizzle), read column p
    int lo = lane & 15;
#pragma unroll
    for (int p = 0; p < 16; p++) sw[(lane << 4) + (p ^ lo)] = v[p];
    __syncwarp();
    int p = lane >> 1, h = lane & 1;
#pragma unroll
    for (int j = 0; j < 16; j++) v[j] = sw[((16 * h + j) << 4) + (p ^ j)];
    __syncwarp();
    // radix-2 butterfly over halves (partner lane = lane^1)
#pragma unroll
    for (int j = 0; j < 16; j++) {
        float2 other = shflx1(v[j]);
        if (h == 0) v[j] = cadd(v[j], other);
        else        v[j] = cmul(csub(other, v[j]), __ldg(&g_w32[j]));
    }
    dft16<-1>(v);  // over j -> q'
}

// ---------------- K2f: filter spectrum -> permuted layout, scaled 1/N ----------------
// One warp per k1. Block 256 = 8 warps. grid 32.
__global__ __launch_bounds__(256, 3) void k_filter_spec(const float2* __restrict__ U,
                                                        float2* __restrict__ Fp) {
    __shared__ float2 sw[8][512];
    int lane = threadIdx.x & 31, w = threadIdx.x >> 5;
    int k1 = (blockIdx.x << 3) + w;
    const float2* u = U + (size_t)PAIRS * N_FFT + (k1 << 9);
    float2 v[16];
#pragma unroll
    for (int r = 0; r < 16; r++) v[r] = u[lane + 32 * r];
    wfft512_fwd(v, sw[w], lane);
    float2* o = Fp + (k1 << 9);
#pragma unroll
    for (int q = 0; q < 16; q++)
        o[q * 32 + lane] = make_float2(v[q].x * INV_N, v[q].y * INV_N);
}

// ---------------- K23: fwd FFT512 + multiply + inv FFT512 + w_N^{+n2 k1} ----------------
// One warp per (row, k1). Block 256 = 8 warps -> 8 consecutive k1. grid (32, 128).
__global__ __launch_bounds__(256, 3) void k_stageB_conv(float2* U, const float2* __restrict__ Fp) {
    __shared__ float2 sw[8][512];
    int lane = threadIdx.x & 31, w = threadIdx.x >> 5;
    int k1 = (blockIdx.x << 3) + w;
    int row = blockIdx.y;
    float2* u = U + (size_t)row * N_FFT + (k1 << 9);
    float2* s = sw[w];
    float2 v[16];
#pragma unroll
    for (int r = 0; r < 16; r++) v[r] = u[lane + 32 * r];
    wfft512_fwd(v, s, lane);

    // multiply by permuted filter spectrum (coalesced)
    const float2* Fr = Fp + (k1 << 9);
#pragma unroll
    for (int q = 0; q < 16; q++) v[q] = cmul(v[q], __ldg(Fr + q * 32 + lane));

    // ---- inverse ----
    int p = lane >> 1, h = lane & 1;
    dft16<1>(v);  // over q' -> E (h=0) / O (h=1) at tau
#pragma unroll
    for (int j = 0; j < 16; j++) {
        float2 other = shflx1(v[j]);
        float2 tw = __ldg(&g_w32[j]);
        if (h == 0) v[j] = cadd(v[j], cmulc(other, tw));      // E + w32^{+j} O
        else        v[j] = csub(other, cmulc(v[j], tw));      // E - w32^{+j} O
    }
    // twiddle w512^{+p t}, t = j + 16h (conj of fwd table, transposed layout)
#pragma unroll
    for (int j = 0; j < 16; j++) v[j] = cmulc(v[j], __ldg(&g_twB[(j + 16 * h) * 16 + p]));
    __syncwarp();
    // transpose back: write [t][p], read row t=lane
#pragma unroll
    for (int j = 0; j < 16; j++) s[((j + 16 * h) << 4) + (p ^ j)] = v[j];
    __syncwarp();
    int lo = lane & 15;
#pragma unroll
    for (int q = 0; q < 16; q++) v[q] = s[(lane << 4) + (q ^ lo)];
    dft16<1>(v);  // over p -> r  (n2 = lane + 32r)

    // outer twiddle w_N^{+n2 k1} and store
    float sb, cb, ss, cs;
    __sincosf((TWO_PI / (float)N_FFT) * (float)(lane * k1), &sb, &cb);
    __sincosf((TWO_PI / 4096.0f) * (float)k1, &ss, &cs);  // w_N^{+32 k1}
    float2 wk = make_float2(cb, sb), wstep = make_float2(cs, ss);
#pragma unroll
    for (int r = 0; r < 16; r++) {
        u[lane + 32 * r] = cmul(v[r], wk);
        wk = cmul(wk, wstep);
    }
}

// ---------------- K1: pack + FFT256 over n1 + w_N twiddle ----------------
// Block: 512 threads = 32 t (FFT lanes) x 16 c (n2 columns). grid (32, 129).
__global__ __launch_bounds__(512) void k_stageA(const float* __restrict__ x,
                                                const float* __restrict__ filt,
                                                float2* __restrict__ U) {
    __shared__ float2 sm[256][16];
    int tx = threadIdx.x;
    int c = tx & 15, t = tx >> 4;
    int n2 = (blockIdx.x << 4) + c;
    int row = blockIdx.y;
    float2 v[8];
    if (row < PAIRS) {
        const float* xa = x + (size_t)row * T_LEN;
        const float* xb = x + (size_t)(row + PAIRS) * T_LEN;
#pragma unroll
        for (int r = 0; r < 4; r++) {
            int n = ((t + 32 * r) << 9) + n2;  // n1 < 128 -> real data
            v[r] = make_float2(__ldg(xa + n), __ldg(xb + n));
        }
    } else {
#pragma unroll
        for (int r = 0; r < 4; r++) {
            int n = ((t + 32 * r) << 9) + n2;
            v[r] = make_float2(__ldg(filt + n), 0.0f);
        }
    }
#pragma unroll
    for (int r = 4; r < 8; r++) v[r] = make_float2(0.0f, 0.0f);

    dft8<-1>(v);  // stage 1 (Ns=1)
#pragma unroll
    for (int r = 0; r < 8; r++) sm[8 * t + r][c] = v[r];
    __syncthreads();
#pragma unroll
    for (int r = 0; r < 8; r++) v[r] = sm[t + 32 * r][c];
    {
        int t8 = t & 7;
#pragma unroll
        for (int r = 1; r < 8; r++) v[r] = cmul(v[r], __ldg(&g_t64[r * 8 + t8]));
    }
    dft8<-1>(v);  // stage 2 (Ns=8)
    __syncthreads();
    {
        int base = ((t >> 3) << 6) + (t & 7);
#pragma unroll
        for (int r = 0; r < 8; r++) sm[base + 8 * r][c] = v[r];
    }
    __syncthreads();

    // stage 3: radix-4, Ns=64; outputs k1 = j + 64m; fuse w_N^{-n2*k1}
    float s64, c64;
    __sincosf(-(TWO_PI / 2048.0f) * (float)n2, &s64, &c64);  // w_N^{-64 n2}
    float2 w64 = make_float2(c64, s64);
    float2* Ur = U + (size_t)row * N_FFT;
#pragma unroll
    for (int g = 0; g < 2; g++) {
        int j = t + 32 * g;
        float2 q[4];
#pragma unroll
        for (int m = 0; m < 4; m++) q[m] = sm[j + 64 * m][c];
#pragma unroll
        for (int m = 1; m < 4; m++) q[m] = cmul(q[m], __ldg(&g_t256[m * 64 + j]));
        dft4<-1>(q);
        float sb, cb;
        __sincosf(-(TWO_PI / (float)N_FFT) * (float)(n2 * j), &sb, &cb);
        float2 wk = make_float2(cb, sb);
#pragma unroll
        for (int m = 0; m < 4; m++) {
            int k1 = j + 64 * m;
            Ur[(k1 << 9) + n2] = cmul(q[m], wk);
            wk = cmul(wk, w64);
        }
    }
}

// ---------------- K4: IFFT256 over k1 + causal unpack ----------------
// Block: 512 threads = 32 t x 16 c (n2 columns). grid (32, 128).
__global__ __launch_bounds__(512) void k_stageAinv(const float2* __restrict__ U,
                                                   float* __restrict__ y) {
    __shared__ float2 sm[256][16];
    int tx = threadIdx.x;
    int c = tx & 15, t = tx >> 4;
    int n2 = (blockIdx.x << 4) + c;
    int row = blockIdx.y;
    const float2* u = U + (size_t)row * N_FFT + n2;
    float2 v[8];
#pragma unroll
    for (int r = 0; r < 8; r++) v[r] = __ldg(u + (size_t)((t + 32 * r) << 9));
    dft8<1>(v);  // stage 1 (Ns=1)
#pragma unroll
    for (int r = 0; r < 8; r++) sm[8 * t + r][c] = v[r];
    __syncthreads();
#pragma unroll
    for (int r = 0; r < 8; r++) v[r] = sm[t + 32 * r][c];
    {
        int t8 = t & 7;
#pragma unroll
        for (int r = 1; r < 8; r++) v[r] = cmulc(v[r], __ldg(&g_t64[r * 8 + t8]));
    }
    dft8<1>(v);  // stage 2 (Ns=8)
    __syncthreads();
    {
        int base = ((t >> 3) << 6) + (t & 7);
#pragma unroll
        for (int r = 0; r < 8; r++) sm[base + 8 * r][c] = v[r];
    }
    __syncthreads();

    float* ya = y + (size_t)row * T_LEN;
    float* yb = y + (size_t)(row + PAIRS) * T_LEN;
#pragma unroll
    for (int g = 0; g < 2; g++) {
        int j = t + 32 * g;
        float2 q[4];
#pragma unroll
        for (int m = 0; m < 4; m++) q[m] = sm[j + 64 * m][c];
#pragma unroll
        for (int m = 1; m < 4; m++) q[m] = cmulc(q[m], __ldg(&g_t256[m * 64 + j]));
        dft4<1>(q);
        // outputs n1 = j + 64m; keep n = 512*n1 + n2 < T  =>  m < 2
#pragma unroll
        for (int m = 0; m < 2; m++) {
            int n = ((j + 64 * m) << 9) + n2;
            ya[n] = q[m].x;
            yb[n] = q[m].y;
        }
    }
}

extern "C" void kernel_launch(void* const* d_in, const int* in_sizes, int n_in,
                              void* d_out, int out_size) {
    const float* x = (const float*)d_in[0];
    const float* filt = (const float*)d_in[1];
    float* y = (float*)d_out;

    float2* U = nullptr;
    float2* F = nullptr;
    cudaGetSymbolAddress((void**)&U, g_buf);
    cudaGetSymbolAddress((void**)&F, g_fspec);

    k_init_tables<<<1, 512>>>();
    k_stageA<<<dim3(32, ROWS_F), 512>>>(x, filt, U);
    k_filter_spec<<<32, 256>>>(U, F);
    k_stageB_conv<<<dim3(32, PAIRS), 256>>>(U, F);
    k_stageAinv<<<dim3(32, PAIRS), 512>>>(U, y);
}